// round 4
// baseline (speedup 1.0000x reference)
#include <cuda_runtime.h>

#define N_NODES 100000
#define N_EDGES 3200000
#define F_IN    128
#define H       32
#define C_OUT   8
#define B_GR    128
#define BN_EPS  1e-5f

// ---------------- scratch (no cudaMalloc allowed) ----------------
__device__ float d_y[N_NODES * H];      // projected features (pre-aggregation)
__device__ float d_hA[N_NODES * H];     // ping
__device__ float d_hB[N_NODES * H];     // pong
__device__ int   d_counts[N_NODES];     // degree (by dst)
__device__ int   d_rowptr[N_NODES];     // CSR row starts
__device__ int   d_cursor[N_NODES];     // scatter cursors
__device__ int   d_col[N_EDGES];        // CSR column (src) indices
__device__ float d_sum[4][H];           // BN sums per layer
__device__ float d_sq[4][H];            // BN sum-of-squares per layer
__device__ float d_pooled[B_GR * H];    // graph pooling accumulators
__device__ float d_cnt[B_GR];           // nodes per graph
__device__ float d_Wf[H * H];           // folded (BN-absorbed) W1 for next layer
__device__ float d_cf[H];               // folded per-row constant
__device__ float d_A3[H];               // final BN affine (applied at pooling)
__device__ float d_Bc3[H];

// ---------------- init ----------------
__global__ void k_zero() {
    int i = blockIdx.x * blockDim.x + threadIdx.x;
    if (i < N_NODES) d_counts[i] = 0;
    if (i < 4 * H) { ((float*)d_sum)[i] = 0.f; ((float*)d_sq)[i] = 0.f; }
    if (i < B_GR * H) d_pooled[i] = 0.f;
    if (i < B_GR) d_cnt[i] = 0.f;
}

// ---------------- CSR build ----------------
__global__ void k_hist(const int* __restrict__ dst) {
    int e = blockIdx.x * blockDim.x + threadIdx.x;
    if (e < N_EDGES) atomicAdd(&d_counts[dst[e]], 1);
}

__global__ void k_scan() {
    __shared__ int s[1024];
    __shared__ int carry;
    int tid = threadIdx.x;
    if (tid == 0) carry = 0;
    __syncthreads();
    for (int base = 0; base < N_NODES; base += 1024) {
        int idx = base + tid;
        int v = (idx < N_NODES) ? d_counts[idx] : 0;
        s[tid] = v;
        __syncthreads();
        #pragma unroll
        for (int off = 1; off < 1024; off <<= 1) {
            int t = (tid >= off) ? s[tid - off] : 0;
            __syncthreads();
            s[tid] += t;
            __syncthreads();
        }
        int excl = s[tid] - v;
        if (idx < N_NODES) {
            int r = carry + excl;
            d_rowptr[idx] = r;
            d_cursor[idx] = r;
        }
        __syncthreads();
        if (tid == 0) carry += s[1023];
        __syncthreads();
    }
}

__global__ void k_scatter(const int* __restrict__ src, const int* __restrict__ dst) {
    int e = blockIdx.x * blockDim.x + threadIdx.x;
    if (e < N_EDGES) {
        int p = atomicAdd(&d_cursor[dst[e]], 1);
        d_col[p] = src[e];
    }
}

// ---------------- layer-0 projection: y = x @ w1_0 ----------------
__global__ __launch_bounds__(256) void k_proj0(const float* __restrict__ x,
                                               const float* __restrict__ w1) {
    __shared__ float sw[F_IN * H];  // 16 KB
    int tid = threadIdx.x;
    for (int i = tid; i < F_IN * H; i += blockDim.x) sw[i] = w1[i];
    __syncthreads();
    int warp = tid >> 5, lane = tid & 31;
    int node = blockIdx.x * (blockDim.x >> 5) + warp;
    if (node >= N_NODES) return;
    const float* xr = x + (size_t)node * F_IN;
    float x0 = xr[lane], x1 = xr[32 + lane], x2 = xr[64 + lane], x3 = xr[96 + lane];
    float acc = 0.f;
    #pragma unroll
    for (int k = 0; k < 32; k++)
        acc += __shfl_sync(0xffffffffu, x0, k) * sw[k * H + lane];
    #pragma unroll
    for (int k = 0; k < 32; k++)
        acc += __shfl_sync(0xffffffffu, x1, k) * sw[(32 + k) * H + lane];
    #pragma unroll
    for (int k = 0; k < 32; k++)
        acc += __shfl_sync(0xffffffffu, x2, k) * sw[(64 + k) * H + lane];
    #pragma unroll
    for (int k = 0; k < 32; k++)
        acc += __shfl_sync(0xffffffffu, x3, k) * sw[(96 + k) * H + lane];
    d_y[node * H + lane] = acc;
}

// ---------------- layers 1-3 projection with folded BN: y = h @ Wf + cf --------
__global__ __launch_bounds__(256) void k_projh(int inSel) {
    __shared__ float sw[H * H];
    __shared__ float sc[H];
    int tid = threadIdx.x;
    for (int i = tid; i < H * H; i += blockDim.x) sw[i] = d_Wf[i];
    if (tid < H) sc[tid] = d_cf[tid];
    __syncthreads();
    const float* hin = inSel ? d_hB : d_hA;
    int warp = tid >> 5, lane = tid & 31;
    int node = blockIdx.x * (blockDim.x >> 5) + warp;
    if (node >= N_NODES) return;
    float hv = hin[node * H + lane];
    float acc = sc[lane];
    #pragma unroll
    for (int k = 0; k < H; k++)
        acc += __shfl_sync(0xffffffffu, hv, k) * sw[k * H + lane];
    d_y[node * H + lane] = acc;
}

// ---------------- aggregate + MLP2 + relu + BN stats (+ optional pooling) ------
__global__ __launch_bounds__(256) void k_mlp(const float* __restrict__ b1,
                                             const float* __restrict__ w2,
                                             const float* __restrict__ b2,
                                             int outSel, int layer, int doPool,
                                             const int* __restrict__ batch) {
    __shared__ float sw[H * H];
    __shared__ float sSum[H];
    __shared__ float sSq[H];
    int tid = threadIdx.x;
    for (int i = tid; i < H * H; i += blockDim.x) sw[i] = w2[i];
    if (tid < H) { sSum[tid] = 0.f; sSq[tid] = 0.f; }
    __syncthreads();
    float* hout = outSel ? d_hB : d_hA;
    int warp = tid >> 5, lane = tid & 31;
    int node = blockIdx.x * (blockDim.x >> 5) + warp;
    float h = 0.f;
    if (node < N_NODES) {
        int start = d_rowptr[node];
        int deg = d_counts[node];
        float a0 = d_y[node * H + lane], a1 = 0.f, a2 = 0.f, a3 = 0.f;
        for (int base = 0; base < deg; base += 32) {
            int rem = deg - base;
            int m = rem < 32 ? rem : 32;
            int nb = (lane < m) ? d_col[start + base + lane] : 0;
            int t = 0;
            for (; t + 4 <= m; t += 4) {
                int j0 = __shfl_sync(0xffffffffu, nb, t);
                int j1 = __shfl_sync(0xffffffffu, nb, t + 1);
                int j2 = __shfl_sync(0xffffffffu, nb, t + 2);
                int j3 = __shfl_sync(0xffffffffu, nb, t + 3);
                a0 += d_y[j0 * H + lane];
                a1 += d_y[j1 * H + lane];
                a2 += d_y[j2 * H + lane];
                a3 += d_y[j3 * H + lane];
            }
            for (; t < m; t++) {
                int j0 = __shfl_sync(0xffffffffu, nb, t);
                a0 += d_y[j0 * H + lane];
            }
        }
        float z = a0 + a1 + a2 + a3 + b1[lane];
        float tt = z > 0.f ? z : 0.f;
        float u = b2[lane];
        #pragma unroll
        for (int k = 0; k < H; k++)
            u += __shfl_sync(0xffffffffu, tt, k) * sw[k * H + lane];
        h = u > 0.f ? u : 0.f;
        hout[node * H + lane] = h;
        if (doPool) {
            int b = batch[node];
            atomicAdd(&d_pooled[b * H + lane], h);
            if (lane == 0) atomicAdd(&d_cnt[b], 1.0f);
        }
    }
    atomicAdd(&sSum[lane], h);
    atomicAdd(&sSq[lane], h * h);
    __syncthreads();
    if (tid < H) {
        atomicAdd(&d_sum[layer][tid], sSum[tid]);
        atomicAdd(&d_sq[layer][tid], sSq[tid]);
    }
}

// ---------------- BN fold into next-layer W1 (or stash for head) ----------------
__global__ void k_fold(int layer, const float* __restrict__ gamma,
                       const float* __restrict__ beta,
                       const float* __restrict__ w1next, int isLast) {
    __shared__ float A[H];
    __shared__ float Bc[H];
    int tid = threadIdx.x;
    if (tid < H) {
        float mean = d_sum[layer][tid] / (float)N_NODES;
        float var = d_sq[layer][tid] / (float)N_NODES - mean * mean;
        float a = gamma[tid] * rsqrtf(var + BN_EPS);
        A[tid] = a;
        Bc[tid] = beta[tid] - a * mean;
    }
    __syncthreads();
    if (isLast) {
        if (tid < H) { d_A3[tid] = A[tid]; d_Bc3[tid] = Bc[tid]; }
    } else {
        if (tid < H * H) {
            int k = tid >> 5;
            d_Wf[tid] = A[k] * w1next[tid];
        }
        if (tid < H) {
            float c = 0.f;
            for (int k = 0; k < H; k++) c += Bc[k] * w1next[k * H + tid];
            d_cf[tid] = c;
        }
    }
}

// ---------------- pooling finalize + fc head + log_softmax ----------------
__global__ void k_head(const float* __restrict__ fc1w, const float* __restrict__ fc1b,
                       const float* __restrict__ fc2w, const float* __restrict__ fc2b,
                       float* __restrict__ out) {
    __shared__ float s1[H * H];
    __shared__ float s2[H * C_OUT];
    __shared__ float sb1[H], sb2[C_OUT], sA[H], sB[H];
    int tid = threadIdx.x;
    for (int i = tid; i < H * H; i += blockDim.x) s1[i] = fc1w[i];
    for (int i = tid; i < H * C_OUT; i += blockDim.x) s2[i] = fc2w[i];
    if (tid < H) { sb1[tid] = fc1b[tid]; sA[tid] = d_A3[tid]; sB[tid] = d_Bc3[tid]; }
    if (tid < C_OUT) sb2[tid] = fc2b[tid];
    __syncthreads();
    if (tid >= B_GR) return;
    float cnt = d_cnt[tid];
    if (cnt < 1.f) cnt = 1.f;
    float m[H];
    #pragma unroll
    for (int k = 0; k < H; k++)
        m[k] = sA[k] * (d_pooled[tid * H + k] / cnt) + sB[k];
    float t[H];
    #pragma unroll
    for (int j = 0; j < H; j++) {
        float acc = sb1[j];
        #pragma unroll
        for (int k = 0; k < H; k++) acc += m[k] * s1[k * H + j];
        t[j] = acc > 0.f ? acc : 0.f;
    }
    float lg[C_OUT];
    float mx = -1e30f;
    #pragma unroll
    for (int c = 0; c < C_OUT; c++) {
        float acc = sb2[c];
        #pragma unroll
        for (int j = 0; j < H; j++) acc += t[j] * s2[j * C_OUT + c];
        lg[c] = acc;
        if (acc > mx) mx = acc;
    }
    float se = 0.f;
    #pragma unroll
    for (int c = 0; c < C_OUT; c++) se += expf(lg[c] - mx);
    float lse = mx + logf(se);
    #pragma unroll
    for (int c = 0; c < C_OUT; c++) out[tid * C_OUT + c] = lg[c] - lse;
}

// ---------------- launcher ----------------
extern "C" void kernel_launch(void* const* d_in, const int* in_sizes, int n_in,
                              void* d_out, int out_size) {
    const float* x     = (const float*)d_in[0];
    const int*   ei    = (const int*)d_in[1];
    const int*   batch = (const int*)d_in[2];
    const float* w1_0  = (const float*)d_in[3];
    const float* b1_0  = (const float*)d_in[4];
    const float* w2_0  = (const float*)d_in[5];
    const float* b2_0  = (const float*)d_in[6];
    const float* g_0   = (const float*)d_in[7];
    const float* be_0  = (const float*)d_in[8];
    const float* w1s   = (const float*)d_in[9];
    const float* b1s   = (const float*)d_in[10];
    const float* w2s   = (const float*)d_in[11];
    const float* b2s   = (const float*)d_in[12];
    const float* gs    = (const float*)d_in[13];
    const float* bes   = (const float*)d_in[14];
    const float* fc1w  = (const float*)d_in[15];
    const float* fc1b  = (const float*)d_in[16];
    const float* fc2w  = (const float*)d_in[17];
    const float* fc2b  = (const float*)d_in[18];
    float* out = (float*)d_out;

    const int* src = ei;
    const int* dst = ei + N_EDGES;

    const int eb = (N_EDGES + 255) / 256;
    const int nb = (N_NODES + 7) / 8;  // 8 warps / block of 256

    k_zero<<<(N_NODES + 255) / 256, 256>>>();
    k_hist<<<eb, 256>>>(dst);
    k_scan<<<1, 1024>>>();
    k_scatter<<<eb, 256>>>(src, dst);

    // layer 0: (F_IN -> H), BN
    k_proj0<<<nb, 256>>>(x, w1_0);
    k_mlp<<<nb, 256>>>(b1_0, w2_0, b2_0, /*outSel=*/0, /*layer=*/0, /*pool=*/0, batch);
    k_fold<<<1, 1024>>>(0, g_0, be_0, w1s + 0 * H * H, 0);

    // layer 1
    k_projh<<<nb, 256>>>(/*inSel=*/0);
    k_mlp<<<nb, 256>>>(b1s + 0 * H, w2s + 0 * H * H, b2s + 0 * H, 1, 1, 0, batch);
    k_fold<<<1, 1024>>>(1, gs + 0 * H, bes + 0 * H, w1s + 1 * H * H, 0);

    // layer 2
    k_projh<<<nb, 256>>>(1);
    k_mlp<<<nb, 256>>>(b1s + 1 * H, w2s + 1 * H * H, b2s + 1 * H, 0, 2, 0, batch);
    k_fold<<<1, 1024>>>(2, gs + 1 * H, bes + 1 * H, w1s + 2 * H * H, 0);

    // layer 3 (+ pooling of raw h; final BN folded into head affine)
    k_projh<<<nb, 256>>>(0);
    k_mlp<<<nb, 256>>>(b1s + 2 * H, w2s + 2 * H * H, b2s + 2 * H, 1, 3, 1, batch);
    k_fold<<<1, 1024>>>(3, gs + 2 * H, bes + 2 * H, w1s, 1);

    k_head<<<1, 128>>>(fc1w, fc1b, fc2w, fc2b, out);
}

// round 5
// speedup vs baseline: 1.2564x; 1.2564x over previous
#include <cuda_runtime.h>

#define N_NODES 100000
#define N_EDGES 3200000
#define F_IN    128
#define H       32
#define C_OUT   8
#define B_GR    128
#define BN_EPS  1e-5f
#define FULL    0xffffffffu

// ---------------- scratch (no cudaMalloc allowed) ----------------
__device__ float d_y[N_NODES * H];      // projected features (pre-aggregation)
__device__ float d_hA[N_NODES * H];     // ping
__device__ float d_hB[N_NODES * H];     // pong
__device__ int   d_counts[N_NODES];     // degree (by dst)
__device__ int   d_cursor[N_NODES];     // scan result / scatter cursors (post-scatter: row end)
__device__ int   d_col[N_EDGES];        // CSR column (src) indices
__device__ float d_sum[4][H];           // BN sums per layer
__device__ float d_sq[4][H];            // BN sum-of-squares per layer
__device__ float d_pooled[B_GR * H];    // graph pooling accumulators
__device__ float d_cnt[B_GR];           // nodes per graph
__device__ float d_Wf[H * H];           // folded (BN-absorbed) W1 for next layer
__device__ float d_cf[H];               // folded per-row constant
__device__ float d_A3[H];               // final BN affine (applied at pooling)
__device__ float d_Bc3[H];

// ---------------- init ----------------
__global__ void k_zero() {
    int i = blockIdx.x * blockDim.x + threadIdx.x;
    if (i < N_NODES) d_counts[i] = 0;
    if (i < 4 * H) { ((float*)d_sum)[i] = 0.f; ((float*)d_sq)[i] = 0.f; }
    if (i < B_GR * H) d_pooled[i] = 0.f;
    if (i < B_GR) d_cnt[i] = 0.f;
}

// ---------------- CSR build ----------------
__global__ void k_hist(const int* __restrict__ dst) {
    int e4 = blockIdx.x * blockDim.x + threadIdx.x;
    if (e4 * 4 < N_EDGES) {
        int4 v = ((const int4*)dst)[e4];
        atomicAdd(&d_counts[v.x], 1);
        atomicAdd(&d_counts[v.y], 1);
        atomicAdd(&d_counts[v.z], 1);
        atomicAdd(&d_counts[v.w], 1);
    }
}

// Exclusive scan of d_counts -> d_cursor. Single block, 4 elems/thread, shfl scan.
__global__ void k_scan() {
    __shared__ int warpsum[32];
    __shared__ int s_carry;
    int tid = threadIdx.x, lane = tid & 31, wid = tid >> 5;
    if (tid == 0) s_carry = 0;
    __syncthreads();
    for (int base = 0; base < N_NODES; base += 4096) {
        int idx = base + tid * 4;
        int4 v = make_int4(0, 0, 0, 0);
        if (idx < N_NODES) v = *(const int4*)&d_counts[idx];  // N_NODES % 4 == 0
        int s1 = v.x + v.y, s2 = s1 + v.z, s3 = s2 + v.w;
        int sum = s3;
        #pragma unroll
        for (int off = 1; off < 32; off <<= 1) {
            int t = __shfl_up_sync(FULL, sum, off);
            if (lane >= off) sum += t;
        }
        if (lane == 31) warpsum[wid] = sum;
        __syncthreads();
        if (wid == 0) {
            int w = warpsum[lane];
            #pragma unroll
            for (int off = 1; off < 32; off <<= 1) {
                int t = __shfl_up_sync(FULL, w, off);
                if (lane >= off) w += t;
            }
            warpsum[lane] = w;
        }
        __syncthreads();
        int warpoff = (wid == 0) ? 0 : warpsum[wid - 1];
        int carry = s_carry;
        int excl = carry + warpoff + (sum - s3);
        if (idx < N_NODES) {
            int4 o;
            o.x = excl; o.y = excl + v.x; o.z = excl + s1; o.w = excl + s2;
            *(int4*)&d_cursor[idx] = o;
        }
        __syncthreads();
        if (tid == 0) s_carry = carry + warpsum[31];
        __syncthreads();
    }
}

__global__ void k_scatter(const int* __restrict__ src, const int* __restrict__ dst) {
    int e4 = blockIdx.x * blockDim.x + threadIdx.x;
    if (e4 * 4 < N_EDGES) {
        int4 d = ((const int4*)dst)[e4];
        int4 s = ((const int4*)src)[e4];
        int p;
        p = atomicAdd(&d_cursor[d.x], 1); d_col[p] = s.x;
        p = atomicAdd(&d_cursor[d.y], 1); d_col[p] = s.y;
        p = atomicAdd(&d_cursor[d.z], 1); d_col[p] = s.z;
        p = atomicAdd(&d_cursor[d.w], 1); d_col[p] = s.w;
    }
}

// ---------------- layer-0 projection: y = x @ w1_0 ----------------
__global__ __launch_bounds__(256) void k_proj0(const float* __restrict__ x,
                                               const float* __restrict__ w1) {
    __shared__ float sw[F_IN * H];  // 16 KB
    int tid = threadIdx.x;
    for (int i = tid; i < F_IN * H; i += blockDim.x) sw[i] = w1[i];
    __syncthreads();
    int warp = tid >> 5, lane = tid & 31;
    int node = blockIdx.x * (blockDim.x >> 5) + warp;
    if (node >= N_NODES) return;
    const float* xr = x + (size_t)node * F_IN;
    float x0 = xr[lane], x1 = xr[32 + lane], x2 = xr[64 + lane], x3 = xr[96 + lane];
    float acc = 0.f;
    #pragma unroll
    for (int k = 0; k < 32; k++)
        acc += __shfl_sync(FULL, x0, k) * sw[k * H + lane];
    #pragma unroll
    for (int k = 0; k < 32; k++)
        acc += __shfl_sync(FULL, x1, k) * sw[(32 + k) * H + lane];
    #pragma unroll
    for (int k = 0; k < 32; k++)
        acc += __shfl_sync(FULL, x2, k) * sw[(64 + k) * H + lane];
    #pragma unroll
    for (int k = 0; k < 32; k++)
        acc += __shfl_sync(FULL, x3, k) * sw[(96 + k) * H + lane];
    d_y[node * H + lane] = acc;
}

// ---------------- layers 1-3 projection with folded BN: y = h @ Wf + cf --------
__global__ __launch_bounds__(256) void k_projh(int inSel) {
    __shared__ float sw[H * H];
    __shared__ float sc[H];
    int tid = threadIdx.x;
    for (int i = tid; i < H * H; i += blockDim.x) sw[i] = d_Wf[i];
    if (tid < H) sc[tid] = d_cf[tid];
    __syncthreads();
    const float* hin = inSel ? d_hB : d_hA;
    int warp = tid >> 5, lane = tid & 31;
    int node = blockIdx.x * (blockDim.x >> 5) + warp;
    if (node >= N_NODES) return;
    float hv = hin[node * H + lane];
    float acc = sc[lane];
    #pragma unroll
    for (int k = 0; k < H; k++)
        acc += __shfl_sync(FULL, hv, k) * sw[k * H + lane];
    d_y[node * H + lane] = acc;
}

// ---------------- aggregate + MLP2 + relu + BN stats (+ optional pooling) ------
// Gather layout: lane = (g<<3)|c4 ; 4 neighbors per warp instruction, 16B/lane.
__global__ __launch_bounds__(256) void k_mlp(const float* __restrict__ b1,
                                             const float* __restrict__ w2,
                                             const float* __restrict__ b2,
                                             int outSel, int layer, int doPool,
                                             const int* __restrict__ batch) {
    __shared__ float sw[H * H];
    __shared__ float sSum[H];
    __shared__ float sSq[H];
    int tid = threadIdx.x;
    for (int i = tid; i < H * H; i += blockDim.x) sw[i] = w2[i];
    if (tid < H) { sSum[tid] = 0.f; sSq[tid] = 0.f; }
    __syncthreads();
    float* hout = outSel ? d_hB : d_hA;
    int warp = tid >> 5, lane = tid & 31;
    int g = lane >> 3;           // neighbor slot 0..3
    int c4 = lane & 7;           // float4 chunk of the H=32 row
    int node = blockIdx.x * (blockDim.x >> 5) + warp;
    float h = 0.f;
    if (node < N_NODES) {
        int deg = d_counts[node];
        int start = d_cursor[node] - deg;   // cursor holds row end post-scatter
        float4 accA = make_float4(0.f, 0.f, 0.f, 0.f);
        float4 accB = make_float4(0.f, 0.f, 0.f, 0.f);
        for (int base = 0; base < deg; base += 32) {
            int rem = deg - base;
            int m = rem < 32 ? rem : 32;
            int nb = (lane < m) ? d_col[start + base + lane] : 0;
            int t = 0;
            for (; t + 8 <= m; t += 8) {
                int ja = __shfl_sync(FULL, nb, t + g);
                int jb = __shfl_sync(FULL, nb, t + 4 + g);
                float4 va = ((const float4*)(d_y + ja * H))[c4];
                float4 vb = ((const float4*)(d_y + jb * H))[c4];
                accA.x += va.x; accA.y += va.y; accA.z += va.z; accA.w += va.w;
                accB.x += vb.x; accB.y += vb.y; accB.z += vb.z; accB.w += vb.w;
            }
            for (; t < m; t += 4) {
                int j = __shfl_sync(FULL, nb, t + g);
                if (t + g < m) {
                    float4 v = ((const float4*)(d_y + j * H))[c4];
                    accA.x += v.x; accA.y += v.y; accA.z += v.z; accA.w += v.w;
                }
            }
        }
        float4 acc;
        acc.x = accA.x + accB.x; acc.y = accA.y + accB.y;
        acc.z = accA.z + accB.z; acc.w = accA.w + accB.w;
        // reduce across the 4 neighbor slots (lanes c4, c4+8, c4+16, c4+24)
        acc.x += __shfl_xor_sync(FULL, acc.x, 8);
        acc.y += __shfl_xor_sync(FULL, acc.y, 8);
        acc.z += __shfl_xor_sync(FULL, acc.z, 8);
        acc.w += __shfl_xor_sync(FULL, acc.w, 8);
        acc.x += __shfl_xor_sync(FULL, acc.x, 16);
        acc.y += __shfl_xor_sync(FULL, acc.y, 16);
        acc.z += __shfl_xor_sync(FULL, acc.z, 16);
        acc.w += __shfl_xor_sync(FULL, acc.w, 16);
        // redistribute to lane = channel layout: channel lane -> chunk lane>>2, comp lane&3
        int sl = lane >> 2;
        float rx = __shfl_sync(FULL, acc.x, sl);
        float ry = __shfl_sync(FULL, acc.y, sl);
        float rz = __shfl_sync(FULL, acc.z, sl);
        float rw = __shfl_sync(FULL, acc.w, sl);
        int cm = lane & 3;
        float aggv = (cm == 0) ? rx : (cm == 1) ? ry : (cm == 2) ? rz : rw;

        float z = aggv + d_y[node * H + lane] + b1[lane];
        float tt = z > 0.f ? z : 0.f;
        float u = b2[lane];
        #pragma unroll
        for (int k = 0; k < H; k++)
            u += __shfl_sync(FULL, tt, k) * sw[k * H + lane];
        h = u > 0.f ? u : 0.f;
        hout[node * H + lane] = h;
        if (doPool) {
            int b = batch[node];
            atomicAdd(&d_pooled[b * H + lane], h);
            if (lane == 0) atomicAdd(&d_cnt[b], 1.0f);
        }
    }
    atomicAdd(&sSum[lane], h);
    atomicAdd(&sSq[lane], h * h);
    __syncthreads();
    if (tid < H) {
        atomicAdd(&d_sum[layer][tid], sSum[tid]);
        atomicAdd(&d_sq[layer][tid], sSq[tid]);
    }
}

// ---------------- BN fold into next-layer W1 (or stash for head) ----------------
__global__ void k_fold(int layer, const float* __restrict__ gamma,
                       const float* __restrict__ beta,
                       const float* __restrict__ w1next, int isLast) {
    __shared__ float A[H];
    __shared__ float Bc[H];
    int tid = threadIdx.x;
    if (tid < H) {
        float mean = d_sum[layer][tid] / (float)N_NODES;
        float var = d_sq[layer][tid] / (float)N_NODES - mean * mean;
        float a = gamma[tid] * rsqrtf(var + BN_EPS);
        A[tid] = a;
        Bc[tid] = beta[tid] - a * mean;
    }
    __syncthreads();
    if (isLast) {
        if (tid < H) { d_A3[tid] = A[tid]; d_Bc3[tid] = Bc[tid]; }
    } else {
        if (tid < H * H) {
            int k = tid >> 5;
            d_Wf[tid] = A[k] * w1next[tid];
        }
        if (tid < H) {
            float c = 0.f;
            for (int k = 0; k < H; k++) c += Bc[k] * w1next[k * H + tid];
            d_cf[tid] = c;
        }
    }
}

// ---------------- pooling finalize + fc head + log_softmax ----------------
__global__ void k_head(const float* __restrict__ fc1w, const float* __restrict__ fc1b,
                       const float* __restrict__ fc2w, const float* __restrict__ fc2b,
                       float* __restrict__ out) {
    __shared__ float s1[H * H];
    __shared__ float s2[H * C_OUT];
    __shared__ float sb1[H], sb2[C_OUT], sA[H], sB[H];
    int tid = threadIdx.x;
    for (int i = tid; i < H * H; i += blockDim.x) s1[i] = fc1w[i];
    for (int i = tid; i < H * C_OUT; i += blockDim.x) s2[i] = fc2w[i];
    if (tid < H) { sb1[tid] = fc1b[tid]; sA[tid] = d_A3[tid]; sB[tid] = d_Bc3[tid]; }
    if (tid < C_OUT) sb2[tid] = fc2b[tid];
    __syncthreads();
    if (tid >= B_GR) return;
    float cnt = d_cnt[tid];
    if (cnt < 1.f) cnt = 1.f;
    float m[H];
    #pragma unroll
    for (int k = 0; k < H; k++)
        m[k] = sA[k] * (d_pooled[tid * H + k] / cnt) + sB[k];
    float t[H];
    #pragma unroll
    for (int j = 0; j < H; j++) {
        float acc = sb1[j];
        #pragma unroll
        for (int k = 0; k < H; k++) acc += m[k] * s1[k * H + j];
        t[j] = acc > 0.f ? acc : 0.f;
    }
    float lg[C_OUT];
    float mx = -1e30f;
    #pragma unroll
    for (int c = 0; c < C_OUT; c++) {
        float acc = sb2[c];
        #pragma unroll
        for (int j = 0; j < H; j++) acc += t[j] * s2[j * C_OUT + c];
        lg[c] = acc;
        if (acc > mx) mx = acc;
    }
    float se = 0.f;
    #pragma unroll
    for (int c = 0; c < C_OUT; c++) se += expf(lg[c] - mx);
    float lse = mx + logf(se);
    #pragma unroll
    for (int c = 0; c < C_OUT; c++) out[tid * C_OUT + c] = lg[c] - lse;
}

// ---------------- launcher ----------------
extern "C" void kernel_launch(void* const* d_in, const int* in_sizes, int n_in,
                              void* d_out, int out_size) {
    const float* x     = (const float*)d_in[0];
    const int*   ei    = (const int*)d_in[1];
    const int*   batch = (const int*)d_in[2];
    const float* w1_0  = (const float*)d_in[3];
    const float* b1_0  = (const float*)d_in[4];
    const float* w2_0  = (const float*)d_in[5];
    const float* b2_0  = (const float*)d_in[6];
    const float* g_0   = (const float*)d_in[7];
    const float* be_0  = (const float*)d_in[8];
    const float* w1s   = (const float*)d_in[9];
    const float* b1s   = (const float*)d_in[10];
    const float* w2s   = (const float*)d_in[11];
    const float* b2s   = (const float*)d_in[12];
    const float* gs    = (const float*)d_in[13];
    const float* bes   = (const float*)d_in[14];
    const float* fc1w  = (const float*)d_in[15];
    const float* fc1b  = (const float*)d_in[16];
    const float* fc2w  = (const float*)d_in[17];
    const float* fc2b  = (const float*)d_in[18];
    float* out = (float*)d_out;

    const int* src = ei;
    const int* dst = ei + N_EDGES;

    const int eb4 = (N_EDGES / 4 + 255) / 256;
    const int nb = (N_NODES + 7) / 8;  // 8 warps / block of 256

    k_zero<<<(N_NODES + 255) / 256, 256>>>();
    k_hist<<<eb4, 256>>>(dst);
    k_scan<<<1, 1024>>>();
    k_scatter<<<eb4, 256>>>(src, dst);

    // layer 0: (F_IN -> H), BN
    k_proj0<<<nb, 256>>>(x, w1_0);
    k_mlp<<<nb, 256>>>(b1_0, w2_0, b2_0, /*outSel=*/0, /*layer=*/0, /*pool=*/0, batch);
    k_fold<<<1, 1024>>>(0, g_0, be_0, w1s + 0 * H * H, 0);

    // layer 1
    k_projh<<<nb, 256>>>(/*inSel=*/0);
    k_mlp<<<nb, 256>>>(b1s + 0 * H, w2s + 0 * H * H, b2s + 0 * H, 1, 1, 0, batch);
    k_fold<<<1, 1024>>>(1, gs + 0 * H, bes + 0 * H, w1s + 1 * H * H, 0);

    // layer 2
    k_projh<<<nb, 256>>>(1);
    k_mlp<<<nb, 256>>>(b1s + 1 * H, w2s + 1 * H * H, b2s + 1 * H, 0, 2, 0, batch);
    k_fold<<<1, 1024>>>(2, gs + 1 * H, bes + 1 * H, w1s + 2 * H * H, 0);

    // layer 3 (+ pooling of raw h; final BN folded into head affine)
    k_projh<<<nb, 256>>>(0);
    k_mlp<<<nb, 256>>>(b1s + 2 * H, w2s + 2 * H * H, b2s + 2 * H, 1, 3, 1, batch);
    k_fold<<<1, 1024>>>(3, gs + 2 * H, bes + 2 * H, w1s, 1);

    k_head<<<1, 128>>>(fc1w, fc1b, fc2w, fc2b, out);
}

// round 8
// speedup vs baseline: 1.4055x; 1.1187x over previous
#include <cuda_runtime.h>
#include <cuda_fp16.h>

#define N_NODES 100000
#define N_EDGES 3200000
#define F_IN    128
#define H       32
#define C_OUT   8
#define B_GR    128
#define BN_EPS  1e-5f
#define FULL    0xffffffffu
#define NBLK    444   // 3 blocks/SM * 148

// ---------------- scratch (no cudaMalloc allowed) ----------------
__device__ float d_y[N_NODES * H];          // projected features fp32 (self term)
__device__ uint4 d_yh[N_NODES * (H / 8)];   // projected features fp16 (gather), 64B/row
__device__ float d_hA[N_NODES * H];         // ping
__device__ float d_hB[N_NODES * H];         // pong
__device__ int   d_counts[N_NODES];         // degree (by dst)
__device__ int   d_cursor[N_NODES];         // scan / scatter cursors (post-scatter: row end)
__device__ int   d_col[N_EDGES];            // CSR column (src) indices
__device__ float d_sum[4][H];
__device__ float d_sq[4][H];
__device__ float d_pooled[B_GR * H];
__device__ float d_cnt[B_GR];
__device__ float d_Wf[H * H];               // folded (BN-absorbed) W1 for next layer
__device__ float d_cf[H];
__device__ float d_A3[H];
__device__ float d_Bc3[H];

// ---------------- init ----------------
__global__ void k_zero() {
    int i = blockIdx.x * blockDim.x + threadIdx.x;
    if (i < N_NODES) d_counts[i] = 0;
    if (i < 4 * H) { ((float*)d_sum)[i] = 0.f; ((float*)d_sq)[i] = 0.f; }
    if (i < B_GR * H) d_pooled[i] = 0.f;
    if (i < B_GR) d_cnt[i] = 0.f;
}

// ---------------- CSR build ----------------
__global__ void k_hist(const int* __restrict__ dst) {
    int e4 = blockIdx.x * blockDim.x + threadIdx.x;
    if (e4 * 4 < N_EDGES) {
        int4 v = ((const int4*)dst)[e4];
        atomicAdd(&d_counts[v.x], 1);
        atomicAdd(&d_counts[v.y], 1);
        atomicAdd(&d_counts[v.z], 1);
        atomicAdd(&d_counts[v.w], 1);
    }
}

__global__ void k_scan() {
    __shared__ int warpsum[32];
    __shared__ int s_carry;
    int tid = threadIdx.x, lane = tid & 31, wid = tid >> 5;
    if (tid == 0) s_carry = 0;
    __syncthreads();
    for (int base = 0; base < N_NODES; base += 4096) {
        int idx = base + tid * 4;
        int4 v = make_int4(0, 0, 0, 0);
        if (idx < N_NODES) v = *(const int4*)&d_counts[idx];
        int s1 = v.x + v.y, s2 = s1 + v.z, s3 = s2 + v.w;
        int sum = s3;
        #pragma unroll
        for (int off = 1; off < 32; off <<= 1) {
            int t = __shfl_up_sync(FULL, sum, off);
            if (lane >= off) sum += t;
        }
        if (lane == 31) warpsum[wid] = sum;
        __syncthreads();
        if (wid == 0) {
            int w = warpsum[lane];
            #pragma unroll
            for (int off = 1; off < 32; off <<= 1) {
                int t = __shfl_up_sync(FULL, w, off);
                if (lane >= off) w += t;
            }
            warpsum[lane] = w;
        }
        __syncthreads();
        int warpoff = (wid == 0) ? 0 : warpsum[wid - 1];
        int carry = s_carry;
        int excl = carry + warpoff + (sum - s3);
        if (idx < N_NODES) {
            int4 o;
            o.x = excl; o.y = excl + v.x; o.z = excl + s1; o.w = excl + s2;
            *(int4*)&d_cursor[idx] = o;
        }
        __syncthreads();
        if (tid == 0) s_carry = carry + warpsum[31];
        __syncthreads();
    }
}

__global__ void k_scatter(const int* __restrict__ src, const int* __restrict__ dst) {
    int e4 = blockIdx.x * blockDim.x + threadIdx.x;
    if (e4 * 4 < N_EDGES) {
        int4 d = ((const int4*)dst)[e4];
        int4 s = ((const int4*)src)[e4];
        int p;
        p = atomicAdd(&d_cursor[d.x], 1); d_col[p] = s.x;
        p = atomicAdd(&d_cursor[d.y], 1); d_col[p] = s.y;
        p = atomicAdd(&d_cursor[d.z], 1); d_col[p] = s.z;
        p = atomicAdd(&d_cursor[d.w], 1); d_col[p] = s.w;
    }
}

// ---------------- layer-0 projection: y = x @ w1_0 (4-warp cooperative) ----------
__global__ __launch_bounds__(256) void k_proj0(const float* __restrict__ x,
                                               const float* __restrict__ w1) {
    __shared__ float part[2][4][H];
    int tid = threadIdx.x, lane = tid & 31, warp = tid >> 5;
    int grp = warp >> 2, wi = warp & 3;  // 2 groups of 4 warps; group handles 1 node
    float wr[32];
    #pragma unroll
    for (int k = 0; k < 32; k++) wr[k] = w1[(wi * 32 + k) * H + lane];

    const int stride = NBLK * 2;
    const int iters = (N_NODES + stride - 1) / stride;
    int node = blockIdx.x * 2 + grp;
    for (int it = 0; it < iters; it++, node += stride) {
        bool valid = node < N_NODES;
        float acc = 0.f;
        if (valid) {
            float xv = x[(size_t)node * F_IN + wi * 32 + lane];
            #pragma unroll
            for (int k = 0; k < 32; k++)
                acc += __shfl_sync(FULL, xv, k) * wr[k];
        }
        part[grp][wi][lane] = acc;
        __syncthreads();
        if (valid && wi == 0) {
            float s = part[grp][0][lane] + part[grp][1][lane]
                    + part[grp][2][lane] + part[grp][3][lane];
            d_y[node * H + lane] = s;
            ((__half*)d_yh)[node * H + lane] = __float2half_rn(s);
        }
        __syncthreads();
    }
}

// ---------------- layers 1-3 projection with folded BN: y = h @ Wf + cf --------
__global__ __launch_bounds__(256) void k_projh(int inSel) {
    int tid = threadIdx.x, lane = tid & 31, warp = tid >> 5;
    float wfc[H];
    #pragma unroll
    for (int k = 0; k < H; k++) wfc[k] = d_Wf[k * H + lane];
    float cfv = d_cf[lane];
    const float* hin = inSel ? d_hB : d_hA;
    for (int node = blockIdx.x * 8 + warp; node < N_NODES; node += NBLK * 8) {
        float hv = hin[node * H + lane];
        float acc = cfv;
        #pragma unroll
        for (int k = 0; k < H; k++)
            acc += __shfl_sync(FULL, hv, k) * wfc[k];
        d_y[node * H + lane] = acc;
        ((__half*)d_yh)[node * H + lane] = __float2half_rn(acc);
    }
}

// ---------------- aggregate + MLP2 + relu + BN stats (+ optional pooling) ------
// fp16 gather: row = 64B = 4 chunks of 16B (8 halves). lane = slot*4 + chunk.
// One warp LDG.128 fetches 8 neighbor rows.
#define ACC8(v) do { __half2 _p; float2 _f;                                  \
    _p = *(__half2*)&(v).x; _f = __half22float2(_p); a0 += _f.x; a1 += _f.y; \
    _p = *(((__half2*)&(v).x) + 1); _f = __half22float2(_p); a2 += _f.x; a3 += _f.y; \
    _p = *(__half2*)&(v).z; _f = __half22float2(_p); a4 += _f.x; a5 += _f.y; \
    _p = *(((__half2*)&(v).z) + 1); _f = __half22float2(_p); a6 += _f.x; a7 += _f.y; } while (0)

__global__ __launch_bounds__(256) void k_mlp(const float* __restrict__ b1,
                                             const float* __restrict__ w2,
                                             const float* __restrict__ b2,
                                             int outSel, int layer, int doPool,
                                             const int* __restrict__ batch) {
    __shared__ float sSum[H];
    __shared__ float sSq[H];
    int tid = threadIdx.x, lane = tid & 31, warp = tid >> 5;
    if (tid < H) { sSum[tid] = 0.f; sSq[tid] = 0.f; }
    __syncthreads();

    float w2c[H];
    #pragma unroll
    for (int k = 0; k < H; k++) w2c[k] = w2[k * H + lane];
    float b1v = b1[lane], b2v = b2[lane];
    float* hout = outSel ? d_hB : d_hA;

    int chunk = lane & 3;   // 16B chunk of the row
    int slot  = lane >> 2;  // neighbor slot 0..7
    float bnS = 0.f, bnQ = 0.f;

    for (int node = blockIdx.x * 8 + warp; node < N_NODES; node += NBLK * 8) {
        int deg = d_counts[node];
        int end = d_cursor[node];
        int start = end - deg;
        float a0 = 0, a1 = 0, a2 = 0, a3 = 0, a4 = 0, a5 = 0, a6 = 0, a7 = 0;
        for (int base = 0; base < deg; base += 32) {
            int m = deg - base; if (m > 32) m = 32;
            int nb = (lane < m) ? d_col[start + base + lane] : 0;
            if (m == 32) {
                int j0 = __shfl_sync(FULL, nb, slot);
                int j1 = __shfl_sync(FULL, nb, 8 + slot);
                int j2 = __shfl_sync(FULL, nb, 16 + slot);
                int j3 = __shfl_sync(FULL, nb, 24 + slot);
                uint4 v0 = d_yh[j0 * (H / 8) + chunk];
                uint4 v1 = d_yh[j1 * (H / 8) + chunk];
                uint4 v2 = d_yh[j2 * (H / 8) + chunk];
                uint4 v3 = d_yh[j3 * (H / 8) + chunk];
                ACC8(v0); ACC8(v1); ACC8(v2); ACC8(v3);
            } else {
                for (int t = 0; t < m; t += 8) {
                    int idx = t + slot;
                    int j = __shfl_sync(FULL, nb, idx < m ? idx : 0);
                    if (idx < m) {
                        uint4 v = d_yh[j * (H / 8) + chunk];
                        ACC8(v);
                    }
                }
            }
        }
        // reduce across the 8 neighbor slots (xor over lane bits 2,3,4)
        #pragma unroll
        for (int off = 4; off <= 16; off <<= 1) {
            a0 += __shfl_xor_sync(FULL, a0, off);
            a1 += __shfl_xor_sync(FULL, a1, off);
            a2 += __shfl_xor_sync(FULL, a2, off);
            a3 += __shfl_xor_sync(FULL, a3, off);
            a4 += __shfl_xor_sync(FULL, a4, off);
            a5 += __shfl_xor_sync(FULL, a5, off);
            a6 += __shfl_xor_sync(FULL, a6, off);
            a7 += __shfl_xor_sync(FULL, a7, off);
        }
        // redistribute: channel `lane` lives in chunk lane>>3 (owned by lane lane>>3), half idx lane&7
        int srcLane = lane >> 3;
        float t0 = __shfl_sync(FULL, a0, srcLane);
        float t1 = __shfl_sync(FULL, a1, srcLane);
        float t2 = __shfl_sync(FULL, a2, srcLane);
        float t3 = __shfl_sync(FULL, a3, srcLane);
        float t4 = __shfl_sync(FULL, a4, srcLane);
        float t5 = __shfl_sync(FULL, a5, srcLane);
        float t6 = __shfl_sync(FULL, a6, srcLane);
        float t7 = __shfl_sync(FULL, a7, srcLane);
        int ix = lane & 7;
        float lo = (ix & 2) ? ((ix & 1) ? t3 : t2) : ((ix & 1) ? t1 : t0);
        float hi = (ix & 2) ? ((ix & 1) ? t7 : t6) : ((ix & 1) ? t5 : t4);
        float aggv = (ix & 4) ? hi : lo;

        float z = aggv + d_y[node * H + lane] + b1v;
        float tt = z > 0.f ? z : 0.f;
        float u = b2v;
        #pragma unroll
        for (int k = 0; k < H; k++)
            u += __shfl_sync(FULL, tt, k) * w2c[k];
        float h = u > 0.f ? u : 0.f;
        hout[node * H + lane] = h;
        if (doPool) {
            int b = batch[node];
            atomicAdd(&d_pooled[b * H + lane], h);
            if (lane == 0) atomicAdd(&d_cnt[b], 1.0f);
        }
        bnS += h; bnQ += h * h;
    }
    atomicAdd(&sSum[lane], bnS);
    atomicAdd(&sSq[lane], bnQ);
    __syncthreads();
    if (tid < H) {
        atomicAdd(&d_sum[layer][tid], sSum[tid]);
        atomicAdd(&d_sq[layer][tid], sSq[tid]);
    }
}

// ---------------- BN fold into next-layer W1 (or stash for head) ----------------
__global__ void k_fold(int layer, const float* __restrict__ gamma,
                       const float* __restrict__ beta,
                       const float* __restrict__ w1next, int isLast) {
    __shared__ float A[H];
    __shared__ float Bc[H];
    int tid = threadIdx.x;
    if (tid < H) {
        float mean = d_sum[layer][tid] / (float)N_NODES;
        float var = d_sq[layer][tid] / (float)N_NODES - mean * mean;
        float a = gamma[tid] * rsqrtf(var + BN_EPS);
        A[tid] = a;
        Bc[tid] = beta[tid] - a * mean;
    }
    __syncthreads();
    if (isLast) {
        if (tid < H) { d_A3[tid] = A[tid]; d_Bc3[tid] = Bc[tid]; }
    } else {
        if (tid < H * H) {
            int k = tid >> 5;
            d_Wf[tid] = A[k] * w1next[tid];
        }
        if (tid < H) {
            float c = 0.f;
            for (int k = 0; k < H; k++) c += Bc[k] * w1next[k * H + tid];
            d_cf[tid] = c;
        }
    }
}

// ---------------- pooling finalize + fc head + log_softmax ----------------
__global__ void k_head(const float* __restrict__ fc1w, const float* __restrict__ fc1b,
                       const float* __restrict__ fc2w, const float* __restrict__ fc2b,
                       float* __restrict__ out) {
    __shared__ float s1[H * H];
    __shared__ float s2[H * C_OUT];
    __shared__ float sb1[H], sb2[C_OUT], sA[H], sB[H];
    int tid = threadIdx.x;
    for (int i = tid; i < H * H; i += blockDim.x) s1[i] = fc1w[i];
    for (int i = tid; i < H * C_OUT; i += blockDim.x) s2[i] = fc2w[i];
    if (tid < H) { sb1[tid] = fc1b[tid]; sA[tid] = d_A3[tid]; sB[tid] = d_Bc3[tid]; }
    if (tid < C_OUT) sb2[tid] = fc2b[tid];
    __syncthreads();
    if (tid >= B_GR) return;
    float cnt = d_cnt[tid];
    if (cnt < 1.f) cnt = 1.f;
    float m[H];
    #pragma unroll
    for (int k = 0; k < H; k++)
        m[k] = sA[k] * (d_pooled[tid * H + k] / cnt) + sB[k];
    float t[H];
    #pragma unroll
    for (int j = 0; j < H; j++) {
        float acc = sb1[j];
        #pragma unroll
        for (int k = 0; k < H; k++) acc += m[k] * s1[k * H + j];
        t[j] = acc > 0.f ? acc : 0.f;
    }
    float lg[C_OUT];
    float mx = -1e30f;
    #pragma unroll
    for (int c = 0; c < C_OUT; c++) {
        float acc = sb2[c];
        #pragma unroll
        for (int j = 0; j < H; j++) acc += t[j] * s2[j * C_OUT + c];
        lg[c] = acc;
        if (acc > mx) mx = acc;
    }
    float se = 0.f;
    #pragma unroll
    for (int c = 0; c < C_OUT; c++) se += expf(lg[c] - mx);
    float lse = mx + logf(se);
    #pragma unroll
    for (int c = 0; c < C_OUT; c++) out[tid * C_OUT + c] = lg[c] - lse;
}

// ---------------- launcher ----------------
extern "C" void kernel_launch(void* const* d_in, const int* in_sizes, int n_in,
                              void* d_out, int out_size) {
    const float* x     = (const float*)d_in[0];
    const int*   ei    = (const int*)d_in[1];
    const int*   batch = (const int*)d_in[2];
    const float* w1_0  = (const float*)d_in[3];
    const float* b1_0  = (const float*)d_in[4];
    const float* w2_0  = (const float*)d_in[5];
    const float* b2_0  = (const float*)d_in[6];
    const float* g_0   = (const float*)d_in[7];
    const float* be_0  = (const float*)d_in[8];
    const float* w1s   = (const float*)d_in[9];
    const float* b1s   = (const float*)d_in[10];
    const float* w2s   = (const float*)d_in[11];
    const float* b2s   = (const float*)d_in[12];
    const float* gs    = (const float*)d_in[13];
    const float* bes   = (const float*)d_in[14];
    const float* fc1w  = (const float*)d_in[15];
    const float* fc1b  = (const float*)d_in[16];
    const float* fc2w  = (const float*)d_in[17];
    const float* fc2b  = (const float*)d_in[18];
    float* out = (float*)d_out;

    const int* src = ei;
    const int* dst = ei + N_EDGES;

    const int eb4 = (N_EDGES / 4 + 255) / 256;

    k_zero<<<(N_NODES + 255) / 256, 256>>>();
    k_hist<<<eb4, 256>>>(dst);
    k_scan<<<1, 1024>>>();
    k_scatter<<<eb4, 256>>>(src, dst);

    // layer 0: (F_IN -> H), BN
    k_proj0<<<NBLK, 256>>>(x, w1_0);
    k_mlp<<<NBLK, 256>>>(b1_0, w2_0, b2_0, /*outSel=*/0, /*layer=*/0, /*pool=*/0, batch);
    k_fold<<<1, 1024>>>(0, g_0, be_0, w1s + 0 * H * H, 0);

    // layer 1
    k_projh<<<NBLK, 256>>>(/*inSel=*/0);
    k_mlp<<<NBLK, 256>>>(b1s + 0 * H, w2s + 0 * H * H, b2s + 0 * H, 1, 1, 0, batch);
    k_fold<<<1, 1024>>>(1, gs + 0 * H, bes + 0 * H, w1s + 1 * H * H, 0);

    // layer 2
    k_projh<<<NBLK, 256>>>(1);
    k_mlp<<<NBLK, 256>>>(b1s + 1 * H, w2s + 1 * H * H, b2s + 1 * H, 0, 2, 0, batch);
    k_fold<<<1, 1024>>>(2, gs + 1 * H, bes + 1 * H, w1s + 2 * H * H, 0);

    // layer 3 (+ pooling; final BN folded into head affine)
    k_projh<<<NBLK, 256>>>(0);
    k_mlp<<<NBLK, 256>>>(b1s + 2 * H, w2s + 2 * H * H, b2s + 2 * H, 1, 3, 1, batch);
    k_fold<<<1, 1024>>>(3, gs + 2 * H, bes + 2 * H, w1s, 1);

    k_head<<<1, 128>>>(fc1w, fc1b, fc2w, fc2b, out);
}

// round 10
// speedup vs baseline: 1.4408x; 1.0251x over previous
#include <cuda_runtime.h>
#include <cuda_fp16.h>

#define N_NODES 100000
#define N_EDGES 3200000
#define F_IN    128
#define H       32
#define C_OUT   8
#define B_GR    128
#define BN_EPS  1e-5f
#define FULL    0xffffffffu
#define NBLK    444   // 3 blocks/SM * 148

// ---------------- scratch (no cudaMalloc allowed) ----------------
__device__ float d_y[N_NODES * H];          // projected features fp32 (self term)
__device__ uint4 d_yh[N_NODES * (H / 8)];   // projected features fp16 (gather), 64B/row
__device__ float d_hA[N_NODES * H];         // ping
__device__ float d_hB[N_NODES * H];         // pong
__device__ int   d_counts[N_NODES];         // degree (by dst)
__device__ int   d_cursor[N_NODES];         // scan / scatter cursors (post-scatter: row end)
__device__ int   d_col[N_EDGES];            // CSR column (src) indices
__device__ float d_sum[4][H];
__device__ float d_sq[4][H];
__device__ float d_pooled[B_GR * H];
__device__ float d_cnt[B_GR];
__device__ float d_Wf[H * H];               // folded (BN-absorbed) W1 for next layer
__device__ float d_cf[H];
__device__ float d_A3[H];
__device__ float d_Bc3[H];

// ---------------- init ----------------
__global__ void k_zero() {
    int i = blockIdx.x * blockDim.x + threadIdx.x;
    if (i < N_NODES) d_counts[i] = 0;
    if (i < 4 * H) { ((float*)d_sum)[i] = 0.f; ((float*)d_sq)[i] = 0.f; }
    if (i < B_GR * H) d_pooled[i] = 0.f;
    if (i < B_GR) d_cnt[i] = 0.f;
}

// ---------------- CSR build ----------------
__global__ void k_hist(const int* __restrict__ dst) {
    int e4 = blockIdx.x * blockDim.x + threadIdx.x;
    if (e4 * 4 < N_EDGES) {
        int4 v = ((const int4*)dst)[e4];
        atomicAdd(&d_counts[v.x], 1);
        atomicAdd(&d_counts[v.y], 1);
        atomicAdd(&d_counts[v.z], 1);
        atomicAdd(&d_counts[v.w], 1);
    }
}

__global__ void k_scan() {
    __shared__ int warpsum[32];
    __shared__ int s_carry;
    int tid = threadIdx.x, lane = tid & 31, wid = tid >> 5;
    if (tid == 0) s_carry = 0;
    __syncthreads();
    for (int base = 0; base < N_NODES; base += 4096) {
        int idx = base + tid * 4;
        int4 v = make_int4(0, 0, 0, 0);
        if (idx < N_NODES) v = *(const int4*)&d_counts[idx];
        int s1 = v.x + v.y, s2 = s1 + v.z, s3 = s2 + v.w;
        int sum = s3;
        #pragma unroll
        for (int off = 1; off < 32; off <<= 1) {
            int t = __shfl_up_sync(FULL, sum, off);
            if (lane >= off) sum += t;
        }
        if (lane == 31) warpsum[wid] = sum;
        __syncthreads();
        if (wid == 0) {
            int w = warpsum[lane];
            #pragma unroll
            for (int off = 1; off < 32; off <<= 1) {
                int t = __shfl_up_sync(FULL, w, off);
                if (lane >= off) w += t;
            }
            warpsum[lane] = w;
        }
        __syncthreads();
        int warpoff = (wid == 0) ? 0 : warpsum[wid - 1];
        int carry = s_carry;
        int excl = carry + warpoff + (sum - s3);
        if (idx < N_NODES) {
            int4 o;
            o.x = excl; o.y = excl + v.x; o.z = excl + s1; o.w = excl + s2;
            *(int4*)&d_cursor[idx] = o;
        }
        __syncthreads();
        if (tid == 0) s_carry = carry + warpsum[31];
        __syncthreads();
    }
}

__global__ void k_scatter(const int* __restrict__ src, const int* __restrict__ dst) {
    int e4 = blockIdx.x * blockDim.x + threadIdx.x;
    if (e4 * 4 < N_EDGES) {
        int4 d = ((const int4*)dst)[e4];
        int4 s = ((const int4*)src)[e4];
        int p0 = atomicAdd(&d_cursor[d.x], 1);
        int p1 = atomicAdd(&d_cursor[d.y], 1);
        int p2 = atomicAdd(&d_cursor[d.z], 1);
        int p3 = atomicAdd(&d_cursor[d.w], 1);
        d_col[p0] = s.x;
        d_col[p1] = s.y;
        d_col[p2] = s.z;
        d_col[p3] = s.w;
    }
}

// ---------------- layer-0 projection: y = x @ w1_0 (4-warp cooperative) ----------
__global__ __launch_bounds__(256) void k_proj0(const float* __restrict__ x,
                                               const float* __restrict__ w1) {
    __shared__ float part[2][4][H];
    int tid = threadIdx.x, lane = tid & 31, warp = tid >> 5;
    int grp = warp >> 2, wi = warp & 3;  // 2 groups of 4 warps; group handles 1 node
    float wr[32];
    #pragma unroll
    for (int k = 0; k < 32; k++) wr[k] = w1[(wi * 32 + k) * H + lane];

    const int stride = NBLK * 2;
    const int iters = (N_NODES + stride - 1) / stride;
    int node = blockIdx.x * 2 + grp;
    for (int it = 0; it < iters; it++, node += stride) {
        bool valid = node < N_NODES;
        float acc = 0.f;
        if (valid) {
            float xv = x[(size_t)node * F_IN + wi * 32 + lane];
            #pragma unroll
            for (int k = 0; k < 32; k++)
                acc += __shfl_sync(FULL, xv, k) * wr[k];
        }
        part[grp][wi][lane] = acc;
        __syncthreads();
        if (valid && wi == 0) {
            float s = part[grp][0][lane] + part[grp][1][lane]
                    + part[grp][2][lane] + part[grp][3][lane];
            d_y[node * H + lane] = s;
            ((__half*)d_yh)[node * H + lane] = __float2half_rn(s);
        }
        __syncthreads();
    }
}

// ---------------- layers 1-3 projection with folded BN: y = h @ Wf + cf --------
__global__ __launch_bounds__(256) void k_projh(int inSel) {
    int tid = threadIdx.x, lane = tid & 31, warp = tid >> 5;
    float wfc[H];
    #pragma unroll
    for (int k = 0; k < H; k++) wfc[k] = d_Wf[k * H + lane];
    float cfv = d_cf[lane];
    const float* hin = inSel ? d_hB : d_hA;
    for (int node = blockIdx.x * 8 + warp; node < N_NODES; node += NBLK * 8) {
        float hv = hin[node * H + lane];
        float acc = cfv;
        #pragma unroll
        for (int k = 0; k < H; k++)
            acc += __shfl_sync(FULL, hv, k) * wfc[k];
        d_y[node * H + lane] = acc;
        ((__half*)d_yh)[node * H + lane] = __float2half_rn(acc);
    }
}

// ---------------- aggregate + MLP2 + relu + BN stats (+ optional pooling) ------
// fp16 gather: row = 64B = 4 chunks of 16B (8 halves). lane = slot*4 + chunk.
// Two nodes per warp iteration for ILP; weights in smem shared by both.
#define ACC8(v, A) do { __half2 _p; float2 _f;                                   \
    _p = *(__half2*)&(v).x; _f = __half22float2(_p); A##0 += _f.x; A##1 += _f.y; \
    _p = *(((__half2*)&(v).x) + 1); _f = __half22float2(_p); A##2 += _f.x; A##3 += _f.y; \
    _p = *(__half2*)&(v).z; _f = __half22float2(_p); A##4 += _f.x; A##5 += _f.y; \
    _p = *(((__half2*)&(v).z) + 1); _f = __half22float2(_p); A##6 += _f.x; A##7 += _f.y; } while (0)

#define RED3(A) do {                          \
    A##0 += __shfl_xor_sync(FULL, A##0, off); \
    A##1 += __shfl_xor_sync(FULL, A##1, off); \
    A##2 += __shfl_xor_sync(FULL, A##2, off); \
    A##3 += __shfl_xor_sync(FULL, A##3, off); \
    A##4 += __shfl_xor_sync(FULL, A##4, off); \
    A##5 += __shfl_xor_sync(FULL, A##5, off); \
    A##6 += __shfl_xor_sync(FULL, A##6, off); \
    A##7 += __shfl_xor_sync(FULL, A##7, off); } while (0)

// redistribute chunk-slot layout -> lane=channel; result in 'res'
#define REDIST(A, res) do {                                \
    float t0 = __shfl_sync(FULL, A##0, srcLane);           \
    float t1 = __shfl_sync(FULL, A##1, srcLane);           \
    float t2 = __shfl_sync(FULL, A##2, srcLane);           \
    float t3 = __shfl_sync(FULL, A##3, srcLane);           \
    float t4 = __shfl_sync(FULL, A##4, srcLane);           \
    float t5 = __shfl_sync(FULL, A##5, srcLane);           \
    float t6 = __shfl_sync(FULL, A##6, srcLane);           \
    float t7 = __shfl_sync(FULL, A##7, srcLane);           \
    float lo = (ix & 2) ? ((ix & 1) ? t3 : t2) : ((ix & 1) ? t1 : t0); \
    float hi = (ix & 2) ? ((ix & 1) ? t7 : t6) : ((ix & 1) ? t5 : t4); \
    res = (ix & 4) ? hi : lo; } while (0)

__global__ __launch_bounds__(256, 3) void k_mlp(const float* __restrict__ b1,
                                                const float* __restrict__ w2,
                                                const float* __restrict__ b2,
                                                int outSel, int layer, int doPool,
                                                const int* __restrict__ batch) {
    __shared__ float sw2[H * H];
    __shared__ float sSum[H];
    __shared__ float sSq[H];
    int tid = threadIdx.x, lane = tid & 31, warp = tid >> 5;
    for (int i = tid; i < H * H; i += 256) sw2[i] = w2[i];
    if (tid < H) { sSum[tid] = 0.f; sSq[tid] = 0.f; }
    __syncthreads();

    float b1v = b1[lane], b2v = b2[lane];
    float* hout = outSel ? d_hB : d_hA;

    const int chunk = lane & 3;   // 16B chunk of the row
    const int slot  = lane >> 2;  // neighbor slot 0..7
    const int srcLane = lane >> 3;
    const int ix = lane & 7;
    const int W = NBLK * 8;       // total warps
    float bnS = 0.f, bnQ = 0.f;

    for (int n0 = blockIdx.x * 8 + warp; n0 < N_NODES; n0 += 2 * W) {
        int n1 = n0 + W;
        bool v1 = n1 < N_NODES;
        int deg0 = d_counts[n0];
        int end0 = d_cursor[n0];
        int deg1 = v1 ? d_counts[n1] : 0;
        int end1 = v1 ? d_cursor[n1] : 0;
        int s0 = end0 - deg0;
        int s1e = end1 - deg1;

        float a0 = 0, a1 = 0, a2 = 0, a3 = 0, a4 = 0, a5 = 0, a6 = 0, a7 = 0;
        float c0 = 0, c1 = 0, c2 = 0, c3 = 0, c4 = 0, c5 = 0, c6 = 0, c7 = 0;

        int maxdeg = deg0 > deg1 ? deg0 : deg1;
        for (int base = 0; base < maxdeg; base += 32) {
            int m0 = deg0 - base;
            int m1 = deg1 - base;
            int nb0 = (lane < m0) ? d_col[s0 + base + lane] : 0;
            int nb1 = (lane < m1) ? d_col[s1e + base + lane] : 0;
            #pragma unroll
            for (int t = 0; t < 32; t += 8) {
                int i = t + slot;
                int j0 = __shfl_sync(FULL, nb0, i);
                int j1 = __shfl_sync(FULL, nb1, i);
                if (i < m0) {
                    uint4 v = d_yh[j0 * (H / 8) + chunk];
                    ACC8(v, a);
                }
                if (i < m1) {
                    uint4 v = d_yh[j1 * (H / 8) + chunk];
                    ACC8(v, c);
                }
            }
        }
        // reduce across the 8 neighbor slots
        #pragma unroll
        for (int off = 4; off <= 16; off <<= 1) { RED3(a); RED3(c); }
        float agg0, agg1;
        REDIST(a, agg0);
        REDIST(c, agg1);

        float z0 = agg0 + d_y[n0 * H + lane] + b1v;
        float tt0 = z0 > 0.f ? z0 : 0.f;
        float tt1 = 0.f;
        if (v1) {
            float z1 = agg1 + d_y[n1 * H + lane] + b1v;
            tt1 = z1 > 0.f ? z1 : 0.f;
        }
        // MLP2: 4-way split accumulators, weight LDS shared by both nodes
        float u0a = 0, u0b = 0, u0c = 0, u0d = 0;
        float u1a = 0, u1b = 0, u1c = 0, u1d = 0;
        #pragma unroll
        for (int k = 0; k < H; k += 4) {
            float w0 = sw2[(k + 0) * H + lane];
            float w1w = sw2[(k + 1) * H + lane];
            float w2w = sw2[(k + 2) * H + lane];
            float w3 = sw2[(k + 3) * H + lane];
            u0a += __shfl_sync(FULL, tt0, k + 0) * w0;
            u1a += __shfl_sync(FULL, tt1, k + 0) * w0;
            u0b += __shfl_sync(FULL, tt0, k + 1) * w1w;
            u1b += __shfl_sync(FULL, tt1, k + 1) * w1w;
            u0c += __shfl_sync(FULL, tt0, k + 2) * w2w;
            u1c += __shfl_sync(FULL, tt1, k + 2) * w2w;
            u0d += __shfl_sync(FULL, tt0, k + 3) * w3;
            u1d += __shfl_sync(FULL, tt1, k + 3) * w3;
        }
        float u0 = (u0a + u0b) + (u0c + u0d) + b2v;
        float h0 = u0 > 0.f ? u0 : 0.f;
        hout[n0 * H + lane] = h0;
        bnS += h0; bnQ += h0 * h0;
        if (doPool) {
            int b = batch[n0];
            atomicAdd(&d_pooled[b * H + lane], h0);
            if (lane == 0) atomicAdd(&d_cnt[b], 1.0f);
        }
        if (v1) {
            float u1 = (u1a + u1b) + (u1c + u1d) + b2v;
            float h1 = u1 > 0.f ? u1 : 0.f;
            hout[n1 * H + lane] = h1;
            bnS += h1; bnQ += h1 * h1;
            if (doPool) {
                int b = batch[n1];
                atomicAdd(&d_pooled[b * H + lane], h1);
                if (lane == 0) atomicAdd(&d_cnt[b], 1.0f);
            }
        }
    }
    atomicAdd(&sSum[lane], bnS);
    atomicAdd(&sSq[lane], bnQ);
    __syncthreads();
    if (tid < H) {
        atomicAdd(&d_sum[layer][tid], sSum[tid]);
        atomicAdd(&d_sq[layer][tid], sSq[tid]);
    }
}

// ---------------- BN fold into next-layer W1 (or stash for head) ----------------
__global__ void k_fold(int layer, const float* __restrict__ gamma,
                       const float* __restrict__ beta,
                       const float* __restrict__ w1next, int isLast) {
    __shared__ float A[H];
    __shared__ float Bc[H];
    int tid = threadIdx.x;
    if (tid < H) {
        float mean = d_sum[layer][tid] / (float)N_NODES;
        float var = d_sq[layer][tid] / (float)N_NODES - mean * mean;
        float a = gamma[tid] * rsqrtf(var + BN_EPS);
        A[tid] = a;
        Bc[tid] = beta[tid] - a * mean;
    }
    __syncthreads();
    if (isLast) {
        if (tid < H) { d_A3[tid] = A[tid]; d_Bc3[tid] = Bc[tid]; }
    } else {
        if (tid < H * H) {
            int k = tid >> 5;
            d_Wf[tid] = A[k] * w1next[tid];
        }
        if (tid < H) {
            float c = 0.f;
            for (int k = 0; k < H; k++) c += Bc[k] * w1next[k * H + tid];
            d_cf[tid] = c;
        }
    }
}

// ---------------- pooling finalize + fc head + log_softmax ----------------
__global__ void k_head(const float* __restrict__ fc1w, const float* __restrict__ fc1b,
                       const float* __restrict__ fc2w, const float* __restrict__ fc2b,
                       float* __restrict__ out) {
    __shared__ float s1[H * H];
    __shared__ float s2[H * C_OUT];
    __shared__ float sb1[H], sb2[C_OUT], sA[H], sB[H];
    int tid = threadIdx.x;
    for (int i = tid; i < H * H; i += blockDim.x) s1[i] = fc1w[i];
    for (int i = tid; i < H * C_OUT; i += blockDim.x) s2[i] = fc2w[i];
    if (tid < H) { sb1[tid] = fc1b[tid]; sA[tid] = d_A3[tid]; sB[tid] = d_Bc3[tid]; }
    if (tid < C_OUT) sb2[tid] = fc2b[tid];
    __syncthreads();
    if (tid >= B_GR) return;
    float cnt = d_cnt[tid];
    if (cnt < 1.f) cnt = 1.f;
    float m[H];
    #pragma unroll
    for (int k = 0; k < H; k++)
        m[k] = sA[k] * (d_pooled[tid * H + k] / cnt) + sB[k];
    float t[H];
    #pragma unroll
    for (int j = 0; j < H; j++) {
        float acc = sb1[j];
        #pragma unroll
        for (int k = 0; k < H; k++) acc += m[k] * s1[k * H + j];
        t[j] = acc > 0.f ? acc : 0.f;
    }
    float lg[C_OUT];
    float mx = -1e30f;
    #pragma unroll
    for (int c = 0; c < C_OUT; c++) {
        float acc = sb2[c];
        #pragma unroll
        for (int j = 0; j < H; j++) acc += t[j] * s2[j * C_OUT + c];
        lg[c] = acc;
        if (acc > mx) mx = acc;
    }
    float se = 0.f;
    #pragma unroll
    for (int c = 0; c < C_OUT; c++) se += expf(lg[c] - mx);
    float lse = mx + logf(se);
    #pragma unroll
    for (int c = 0; c < C_OUT; c++) out[tid * C_OUT + c] = lg[c] - lse;
}

// ---------------- launcher ----------------
extern "C" void kernel_launch(void* const* d_in, const int* in_sizes, int n_in,
                              void* d_out, int out_size) {
    const float* x     = (const float*)d_in[0];
    const int*   ei    = (const int*)d_in[1];
    const int*   batch = (const int*)d_in[2];
    const float* w1_0  = (const float*)d_in[3];
    const float* b1_0  = (const float*)d_in[4];
    const float* w2_0  = (const float*)d_in[5];
    const float* b2_0  = (const float*)d_in[6];
    const float* g_0   = (const float*)d_in[7];
    const float* be_0  = (const float*)d_in[8];
    const float* w1s   = (const float*)d_in[9];
    const float* b1s   = (const float*)d_in[10];
    const float* w2s   = (const float*)d_in[11];
    const float* b2s   = (const float*)d_in[12];
    const float* gs    = (const float*)d_in[13];
    const float* bes   = (const float*)d_in[14];
    const float* fc1w  = (const float*)d_in[15];
    const float* fc1b  = (const float*)d_in[16];
    const float* fc2w  = (const float*)d_in[17];
    const float* fc2b  = (const float*)d_in[18];
    float* out = (float*)d_out;

    const int* src = ei;
    const int* dst = ei + N_EDGES;

    const int eb4 = (N_EDGES / 4 + 255) / 256;

    k_zero<<<(N_NODES + 255) / 256, 256>>>();
    k_hist<<<eb4, 256>>>(dst);
    k_scan<<<1, 1024>>>();
    k_scatter<<<eb4, 256>>>(src, dst);

    // layer 0: (F_IN -> H), BN
    k_proj0<<<NBLK, 256>>>(x, w1_0);
    k_mlp<<<NBLK, 256>>>(b1_0, w2_0, b2_0, /*outSel=*/0, /*layer=*/0, /*pool=*/0, batch);
    k_fold<<<1, 1024>>>(0, g_0, be_0, w1s + 0 * H * H, 0);

    // layer 1
    k_projh<<<NBLK, 256>>>(/*inSel=*/0);
    k_mlp<<<NBLK, 256>>>(b1s + 0 * H, w2s + 0 * H * H, b2s + 0 * H, 1, 1, 0, batch);
    k_fold<<<1, 1024>>>(1, gs + 0 * H, bes + 0 * H, w1s + 1 * H * H, 0);

    // layer 2
    k_projh<<<NBLK, 256>>>(1);
    k_mlp<<<NBLK, 256>>>(b1s + 1 * H, w2s + 1 * H * H, b2s + 1 * H, 0, 2, 0, batch);
    k_fold<<<1, 1024>>>(2, gs + 1 * H, bes + 1 * H, w1s + 2 * H * H, 0);

    // layer 3 (+ pooling; final BN folded into head affine)
    k_projh<<<NBLK, 256>>>(0);
    k_mlp<<<NBLK, 256>>>(b1s + 2 * H, w2s + 2 * H * H, b2s + 2 * H, 1, 3, 1, batch);
    k_fold<<<1, 1024>>>(3, gs + 2 * H, bes + 2 * H, w1s, 1);

    k_head<<<1, 128>>>(fc1w, fc1b, fc2w, fc2b, out);
}

// round 15
// speedup vs baseline: 1.5743x; 1.0927x over previous
#include <cuda_runtime.h>
#include <cuda_fp16.h>

#define N_NODES 100000
#define N_EDGES 3200000
#define F_IN    128
#define H       32
#define C_OUT   8
#define B_GR    128
#define BN_EPS  1e-5f
#define FULL    0xffffffffu
#define NBLK    444   // 3 blocks/SM * 148

// ---------------- scratch (no cudaMalloc allowed) ----------------
__device__ uint4  d_yh[N_NODES * (H / 8)];   // projected features fp16 (gather), 64B/row
__device__ __half d_hA[N_NODES * H];         // ping (fp16)
__device__ __half d_hB[N_NODES * H];         // pong (fp16)
__device__ int    d_counts[N_NODES];         // degree (by dst)
__device__ int    d_cursor[N_NODES];         // scan / scatter cursors (post-scatter: row end)
__device__ int    d_col[N_EDGES];            // CSR column (src) indices
__device__ float  d_sum[4][H];
__device__ float  d_sq[4][H];
__device__ float  d_pooled[B_GR * H];
__device__ float  d_cnt[B_GR];
__device__ float  d_Wf[H * H];               // folded (BN-absorbed) W1 for next layer
__device__ float  d_cf[H];
__device__ float  d_A3[H];
__device__ float  d_Bc3[H];

// ---------------- init ----------------
__global__ void k_zero() {
    int i = blockIdx.x * blockDim.x + threadIdx.x;
    if (i < N_NODES) d_counts[i] = 0;
    if (i < 4 * H) { ((float*)d_sum)[i] = 0.f; ((float*)d_sq)[i] = 0.f; }
    if (i < B_GR * H) d_pooled[i] = 0.f;
    if (i < B_GR) d_cnt[i] = 0.f;
}

// ---------------- CSR build ----------------
__global__ void k_hist(const int* __restrict__ dst) {
    int e4 = blockIdx.x * blockDim.x + threadIdx.x;
    if (e4 * 4 < N_EDGES) {
        int4 v = ((const int4*)dst)[e4];
        atomicAdd(&d_counts[v.x], 1);
        atomicAdd(&d_counts[v.y], 1);
        atomicAdd(&d_counts[v.z], 1);
        atomicAdd(&d_counts[v.w], 1);
    }
}

__global__ void k_scan() {
    __shared__ int warpsum[32];
    __shared__ int s_carry;
    int tid = threadIdx.x, lane = tid & 31, wid = tid >> 5;
    if (tid == 0) s_carry = 0;
    __syncthreads();
    for (int base = 0; base < N_NODES; base += 4096) {
        int idx = base + tid * 4;
        int4 v = make_int4(0, 0, 0, 0);
        if (idx < N_NODES) v = *(const int4*)&d_counts[idx];
        int s1 = v.x + v.y, s2 = s1 + v.z, s3 = s2 + v.w;
        int sum = s3;
        #pragma unroll
        for (int off = 1; off < 32; off <<= 1) {
            int t = __shfl_up_sync(FULL, sum, off);
            if (lane >= off) sum += t;
        }
        if (lane == 31) warpsum[wid] = sum;
        __syncthreads();
        if (wid == 0) {
            int w = warpsum[lane];
            #pragma unroll
            for (int off = 1; off < 32; off <<= 1) {
                int t = __shfl_up_sync(FULL, w, off);
                if (lane >= off) w += t;
            }
            warpsum[lane] = w;
        }
        __syncthreads();
        int warpoff = (wid == 0) ? 0 : warpsum[wid - 1];
        int carry = s_carry;
        int excl = carry + warpoff + (sum - s3);
        if (idx < N_NODES) {
            int4 o;
            o.x = excl; o.y = excl + v.x; o.z = excl + s1; o.w = excl + s2;
            *(int4*)&d_cursor[idx] = o;
        }
        __syncthreads();
        if (tid == 0) s_carry = carry + warpsum[31];
        __syncthreads();
    }
}

__global__ void k_scatter(const int* __restrict__ src, const int* __restrict__ dst) {
    int e4 = blockIdx.x * blockDim.x + threadIdx.x;
    if (e4 * 4 < N_EDGES) {
        int4 d = ((const int4*)dst)[e4];
        int4 s = ((const int4*)src)[e4];
        int p0 = atomicAdd(&d_cursor[d.x], 1);
        int p1 = atomicAdd(&d_cursor[d.y], 1);
        int p2 = atomicAdd(&d_cursor[d.z], 1);
        int p3 = atomicAdd(&d_cursor[d.w], 1);
        d_col[p0] = s.x;
        d_col[p1] = s.y;
        d_col[p2] = s.z;
        d_col[p3] = s.w;
    }
}

// ---------------- layer-0 projection: y = x @ w1_0 (4-warp cooperative) ----------
__global__ __launch_bounds__(256) void k_proj0(const float* __restrict__ x,
                                               const float* __restrict__ w1) {
    __shared__ float part[2][4][H];
    int tid = threadIdx.x, lane = tid & 31, warp = tid >> 5;
    int grp = warp >> 2, wi = warp & 3;  // 2 groups of 4 warps; group handles 1 node
    float wr[32];
    #pragma unroll
    for (int k = 0; k < 32; k++) wr[k] = w1[(wi * 32 + k) * H + lane];

    const int stride = NBLK * 2;
    const int iters = (N_NODES + stride - 1) / stride;
    int node = blockIdx.x * 2 + grp;
    for (int it = 0; it < iters; it++, node += stride) {
        bool valid = node < N_NODES;
        float acc = 0.f;
        if (valid) {
            float xv = x[(size_t)node * F_IN + wi * 32 + lane];
            #pragma unroll
            for (int k = 0; k < 32; k++)
                acc += __shfl_sync(FULL, xv, k) * wr[k];
        }
        part[grp][wi][lane] = acc;
        __syncthreads();
        if (valid && wi == 0) {
            float s = part[grp][0][lane] + part[grp][1][lane]
                    + part[grp][2][lane] + part[grp][3][lane];
            ((__half*)d_yh)[node * H + lane] = __float2half_rn(s);
        }
        __syncthreads();
    }
}

// ---------------- layers 1-3 projection with folded BN: y = h @ Wf + cf --------
__global__ __launch_bounds__(256) void k_projh(int inSel) {
    int tid = threadIdx.x, lane = tid & 31, warp = tid >> 5;
    float wfc[H];
    #pragma unroll
    for (int k = 0; k < H; k++) wfc[k] = d_Wf[k * H + lane];
    float cfv = d_cf[lane];
    const __half* hin = inSel ? d_hB : d_hA;
    for (int node = blockIdx.x * 8 + warp; node < N_NODES; node += NBLK * 8) {
        float hv = __half2float(hin[node * H + lane]);
        float acc = cfv;
        #pragma unroll
        for (int k = 0; k < H; k++)
            acc += __shfl_sync(FULL, hv, k) * wfc[k];
        ((__half*)d_yh)[node * H + lane] = __float2half_rn(acc);
    }
}

// ---------------- aggregate + MLP2 + relu + BN stats (+ optional pooling) ------
// fp16 gather: row = 64B = 4 chunks of 16B. lane = slot*4 + chunk (8 slots).
// Tiles accumulated in half2 (<=4 adds), flushed to fp32 per tile.
// Slot reduction via smem transpose (no shfl chains).

#define HACC4(v, Hc) do {                                   \
    Hc[0] = __hadd2(Hc[0], ((const __half2*)&(v))[0]);      \
    Hc[1] = __hadd2(Hc[1], ((const __half2*)&(v))[1]);      \
    Hc[2] = __hadd2(Hc[2], ((const __half2*)&(v))[2]);      \
    Hc[3] = __hadd2(Hc[3], ((const __half2*)&(v))[3]); } while (0)

#define FLUSH4(Hc, F) do { float2 _f;                        \
    _f = __half22float2(Hc[0]); F[0] += _f.x; F[1] += _f.y;  \
    _f = __half22float2(Hc[1]); F[2] += _f.x; F[3] += _f.y;  \
    _f = __half22float2(Hc[2]); F[4] += _f.x; F[5] += _f.y;  \
    _f = __half22float2(Hc[3]); F[6] += _f.x; F[7] += _f.y; } while (0)

#define RPAD 36  // padded row (floats) for conflict-free slot-sum reads

__global__ __launch_bounds__(256, 3) void k_mlp(const float* __restrict__ b1,
                                                const float* __restrict__ w2,
                                                const float* __restrict__ b2,
                                                int outSel, int layer, int doPool,
                                                const int* __restrict__ batch) {
    __shared__ float sw2[H * H];
    __shared__ float sSum[H];
    __shared__ float sSq[H];
    __shared__ float sred[8][2][8 * RPAD];   // [warp][node][slot*RPAD + ch]
    int tid = threadIdx.x, lane = tid & 31, warp = tid >> 5;
    for (int i = tid; i < H * H; i += 256) sw2[i] = w2[i];
    if (tid < H) { sSum[tid] = 0.f; sSq[tid] = 0.f; }
    __syncthreads();

    float b1v = b1[lane], b2v = b2[lane];
    __half* hout = outSel ? d_hB : d_hA;
    const __half* selfh = (const __half*)d_yh;

    const int chunk = lane & 3;   // 16B chunk of the row
    const int slot  = lane >> 2;  // neighbor slot 0..7
    const int sbase = slot * RPAD + chunk * 8;
    const int W = NBLK * 8;       // total warps
    float bnS = 0.f, bnQ = 0.f;

    for (int n0 = blockIdx.x * 8 + warp; n0 < N_NODES; n0 += 2 * W) {
        int n1 = n0 + W;
        bool v1 = n1 < N_NODES;
        int deg0 = d_counts[n0];
        int end0 = d_cursor[n0];
        int deg1 = v1 ? d_counts[n1] : 0;
        int end1 = v1 ? d_cursor[n1] : 0;
        int s0 = end0 - deg0;
        int s1e = end1 - deg1;

        float F0[8] = {0, 0, 0, 0, 0, 0, 0, 0};
        float F1[8] = {0, 0, 0, 0, 0, 0, 0, 0};

        int maxdeg = deg0 > deg1 ? deg0 : deg1;
        for (int base = 0; base < maxdeg; base += 32) {
            int m0 = deg0 - base;
            int m1 = deg1 - base;
            int nb0 = (lane < m0) ? d_col[s0 + base + lane] : 0;
            int nb1 = (lane < m1) ? d_col[s1e + base + lane] : 0;
            __half2 hz = __float2half2_rn(0.f);
            __half2 h0c[4] = {hz, hz, hz, hz};
            __half2 h1c[4] = {hz, hz, hz, hz};
            #pragma unroll
            for (int t = 0; t < 32; t += 8) {
                int i = t + slot;
                int j0 = __shfl_sync(FULL, nb0, i);
                int j1 = __shfl_sync(FULL, nb1, i);
                if (i < m0) {
                    uint4 v = d_yh[j0 * (H / 8) + chunk];
                    HACC4(v, h0c);
                }
                if (i < m1) {
                    uint4 v = d_yh[j1 * (H / 8) + chunk];
                    HACC4(v, h1c);
                }
            }
            FLUSH4(h0c, F0);
            FLUSH4(h1c, F1);
        }

        // slot reduction via smem transpose
        *(float4*)&sred[warp][0][sbase]     = make_float4(F0[0], F0[1], F0[2], F0[3]);
        *(float4*)&sred[warp][0][sbase + 4] = make_float4(F0[4], F0[5], F0[6], F0[7]);
        *(float4*)&sred[warp][1][sbase]     = make_float4(F1[0], F1[1], F1[2], F1[3]);
        *(float4*)&sred[warp][1][sbase + 4] = make_float4(F1[4], F1[5], F1[6], F1[7]);
        __syncwarp();
        float agg0 = 0.f, agg1 = 0.f;
        #pragma unroll
        for (int s = 0; s < 8; s++) {
            agg0 += sred[warp][0][s * RPAD + lane];
            agg1 += sred[warp][1][s * RPAD + lane];
        }
        __syncwarp();

        float z0 = agg0 + __half2float(selfh[n0 * H + lane]) + b1v;
        float tt0 = z0 > 0.f ? z0 : 0.f;
        float tt1 = 0.f;
        if (v1) {
            float z1 = agg1 + __half2float(selfh[n1 * H + lane]) + b1v;
            tt1 = z1 > 0.f ? z1 : 0.f;
        }
        // MLP2: 4-way split accumulators, weight LDS shared by both nodes
        float u0a = 0, u0b = 0, u0c = 0, u0d = 0;
        float u1a = 0, u1b = 0, u1c = 0, u1d = 0;
        #pragma unroll
        for (int k = 0; k < H; k += 4) {
            float w0 = sw2[(k + 0) * H + lane];
            float w1w = sw2[(k + 1) * H + lane];
            float w2w = sw2[(k + 2) * H + lane];
            float w3 = sw2[(k + 3) * H + lane];
            u0a += __shfl_sync(FULL, tt0, k + 0) * w0;
            u1a += __shfl_sync(FULL, tt1, k + 0) * w0;
            u0b += __shfl_sync(FULL, tt0, k + 1) * w1w;
            u1b += __shfl_sync(FULL, tt1, k + 1) * w1w;
            u0c += __shfl_sync(FULL, tt0, k + 2) * w2w;
            u1c += __shfl_sync(FULL, tt1, k + 2) * w2w;
            u0d += __shfl_sync(FULL, tt0, k + 3) * w3;
            u1d += __shfl_sync(FULL, tt1, k + 3) * w3;
        }
        float u0 = (u0a + u0b) + (u0c + u0d) + b2v;
        float h0 = u0 > 0.f ? u0 : 0.f;
        hout[n0 * H + lane] = __float2half_rn(h0);
        bnS += h0; bnQ += h0 * h0;
        if (doPool) {
            int b = batch[n0];
            atomicAdd(&d_pooled[b * H + lane], h0);
            if (lane == 0) atomicAdd(&d_cnt[b], 1.0f);
        }
        if (v1) {
            float u1 = (u1a + u1b) + (u1c + u1d) + b2v;
            float h1 = u1 > 0.f ? u1 : 0.f;
            hout[n1 * H + lane] = __float2half_rn(h1);
            bnS += h1; bnQ += h1 * h1;
            if (doPool) {
                int b = batch[n1];
                atomicAdd(&d_pooled[b * H + lane], h1);
                if (lane == 0) atomicAdd(&d_cnt[b], 1.0f);
            }
        }
    }
    atomicAdd(&sSum[lane], bnS);
    atomicAdd(&sSq[lane], bnQ);
    __syncthreads();
    if (tid < H) {
        atomicAdd(&d_sum[layer][tid], sSum[tid]);
        atomicAdd(&d_sq[layer][tid], sSq[tid]);
    }
}

// ---------------- BN fold into next-layer W1 (or stash for head) ----------------
__global__ void k_fold(int layer, const float* __restrict__ gamma,
                       const float* __restrict__ beta,
                       const float* __restrict__ w1next, int isLast) {
    __shared__ float A[H];
    __shared__ float Bc[H];
    int tid = threadIdx.x;
    if (tid < H) {
        float mean = d_sum[layer][tid] / (float)N_NODES;
        float var = d_sq[layer][tid] / (float)N_NODES - mean * mean;
        float a = gamma[tid] * rsqrtf(var + BN_EPS);
        A[tid] = a;
        Bc[tid] = beta[tid] - a * mean;
    }
    __syncthreads();
    if (isLast) {
        if (tid < H) { d_A3[tid] = A[tid]; d_Bc3[tid] = Bc[tid]; }
    } else {
        if (tid < H * H) {
            int k = tid >> 5;
            d_Wf[tid] = A[k] * w1next[tid];
        }
        if (tid < H) {
            float c = 0.f;
            for (int k = 0; k < H; k++) c += Bc[k] * w1next[k * H + tid];
            d_cf[tid] = c;
        }
    }
}

// ---------------- pooling finalize + fc head + log_softmax ----------------
__global__ void k_head(const float* __restrict__ fc1w, const float* __restrict__ fc1b,
                       const float* __restrict__ fc2w, const float* __restrict__ fc2b,
                       float* __restrict__ out) {
    __shared__ float s1[H * H];
    __shared__ float s2[H * C_OUT];
    __shared__ float sb1[H], sb2[C_OUT], sA[H], sB[H];
    int tid = threadIdx.x;
    for (int i = tid; i < H * H; i += blockDim.x) s1[i] = fc1w[i];
    for (int i = tid; i < H * C_OUT; i += blockDim.x) s2[i] = fc2w[i];
    if (tid < H) { sb1[tid] = fc1b[tid]; sA[tid] = d_A3[tid]; sB[tid] = d_Bc3[tid]; }
    if (tid < C_OUT) sb2[tid] = fc2b[tid];
    __syncthreads();
    if (tid >= B_GR) return;
    float cnt = d_cnt[tid];
    if (cnt < 1.f) cnt = 1.f;
    float m[H];
    #pragma unroll
    for (int k = 0; k < H; k++)
        m[k] = sA[k] * (d_pooled[tid * H + k] / cnt) + sB[k];
    float t[H];
    #pragma unroll
    for (int j = 0; j < H; j++) {
        float acc = sb1[j];
        #pragma unroll
        for (int k = 0; k < H; k++) acc += m[k] * s1[k * H + j];
        t[j] = acc > 0.f ? acc : 0.f;
    }
    float lg[C_OUT];
    float mx = -1e30f;
    #pragma unroll
    for (int c = 0; c < C_OUT; c++) {
        float acc = sb2[c];
        #pragma unroll
        for (int j = 0; j < H; j++) acc += t[j] * s2[j * C_OUT + c];
        lg[c] = acc;
        if (acc > mx) mx = acc;
    }
    float se = 0.f;
    #pragma unroll
    for (int c = 0; c < C_OUT; c++) se += expf(lg[c] - mx);
    float lse = mx + logf(se);
    #pragma unroll
    for (int c = 0; c < C_OUT; c++) out[tid * C_OUT + c] = lg[c] - lse;
}

// ---------------- launcher ----------------
extern "C" void kernel_launch(void* const* d_in, const int* in_sizes, int n_in,
                              void* d_out, int out_size) {
    const float* x     = (const float*)d_in[0];
    const int*   ei    = (const int*)d_in[1];
    const int*   batch = (const int*)d_in[2];
    const float* w1_0  = (const float*)d_in[3];
    const float* b1_0  = (const float*)d_in[4];
    const float* w2_0  = (const float*)d_in[5];
    const float* b2_0  = (const float*)d_in[6];
    const float* g_0   = (const float*)d_in[7];
    const float* be_0  = (const float*)d_in[8];
    const float* w1s   = (const float*)d_in[9];
    const float* b1s   = (const float*)d_in[10];
    const float* w2s   = (const float*)d_in[11];
    const float* b2s   = (const float*)d_in[12];
    const float* gs    = (const float*)d_in[13];
    const float* bes   = (const float*)d_in[14];
    const float* fc1w  = (const float*)d_in[15];
    const float* fc1b  = (const float*)d_in[16];
    const float* fc2w  = (const float*)d_in[17];
    const float* fc2b  = (const float*)d_in[18];
    float* out = (float*)d_out;

    const int* src = ei;
    const int* dst = ei + N_EDGES;

    const int eb4 = (N_EDGES / 4 + 255) / 256;

    k_zero<<<(N_NODES + 255) / 256, 256>>>();
    k_hist<<<eb4, 256>>>(dst);
    k_scan<<<1, 1024>>>();
    k_scatter<<<eb4, 256>>>(src, dst);

    // layer 0: (F_IN -> H), BN
    k_proj0<<<NBLK, 256>>>(x, w1_0);
    k_mlp<<<NBLK, 256>>>(b1_0, w2_0, b2_0, /*outSel=*/0, /*layer=*/0, /*pool=*/0, batch);
    k_fold<<<1, 1024>>>(0, g_0, be_0, w1s + 0 * H * H, 0);

    // layer 1
    k_projh<<<NBLK, 256>>>(/*inSel=*/0);
    k_mlp<<<NBLK, 256>>>(b1s + 0 * H, w2s + 0 * H * H, b2s + 0 * H, 1, 1, 0, batch);
    k_fold<<<1, 1024>>>(1, gs + 0 * H, bes + 0 * H, w1s + 1 * H * H, 0);

    // layer 2
    k_projh<<<NBLK, 256>>>(1);
    k_mlp<<<NBLK, 256>>>(b1s + 1 * H, w2s + 1 * H * H, b2s + 1 * H, 0, 2, 0, batch);
    k_fold<<<1, 1024>>>(2, gs + 1 * H, bes + 1 * H, w1s + 2 * H * H, 0);

    // layer 3 (+ pooling; final BN folded into head affine)
    k_projh<<<NBLK, 256>>>(0);
    k_mlp<<<NBLK, 256>>>(b1s + 2 * H, w2s + 2 * H * H, b2s + 2 * H, 1, 3, 1, batch);
    k_fold<<<1, 1024>>>(3, gs + 2 * H, bes + 2 * H, w1s, 1);

    k_head<<<1, 128>>>(fc1w, fc1b, fc2w, fc2b, out);
}